// round 10
// baseline (speedup 1.0000x reference)
#include <cuda_runtime.h>
#include <cuda_bf16.h>

// SmoothnessLoss: loss = mean_i( (sHat_i - sY_i)^2 ), i in [0, W), W = N-k-1
// s_i = sum_{j<k} | x[i+j] - mean_j |, k = 64.
// Persistent kernel, WPT=8, DYNAMIC subtile scheduling (atomic ticket) to kill
// cross-SM completion spread. Deterministic: per-subtile partial slots + fixed
// order final reduction.

#define K_WIN 64
#define BLOCK 256
#define WPT 8
#define SUBTILE (BLOCK * WPT)                // 2048 windows per subtile
#define GRID 296                             // 2 blocks/SM x 148 SMs
#define MAX_SUB 1024                         // >= ceil(1e6/2048) = 489

typedef unsigned long long u64;

__device__ float g_partials[MAX_SUB];
__device__ unsigned int g_ticket = 0;
__device__ unsigned int g_count = 0;

__device__ __forceinline__ u64 addx2(u64 a, u64 b) {
    u64 r; asm("add.rn.f32x2 %0, %1, %2;" : "=l"(r) : "l"(a), "l"(b)); return r;
}
__device__ __forceinline__ u64 pk(float lo, float hi) {
    u64 r; asm("mov.b64 %0, {%1, %2};" : "=l"(r) : "f"(lo), "f"(hi)); return r;
}
__device__ __forceinline__ void upk(u64 p, float& lo, float& hi) {
    asm("mov.b64 {%0, %1}, %2;" : "=f"(lo), "=f"(hi) : "l"(p));
}
__device__ __forceinline__ u64 absx2(u64 a) { return a & 0x7FFFFFFF7FFFFFFFULL; }
__device__ __forceinline__ float sum2(u64 a) { float l, h; upk(a, l, h); return l + h; }

// Opaque 16B load (prevents cross-pass CSE; placement fixed by program order).
__device__ __forceinline__ void ldg2(const ulonglong2* p, u64& x, u64& y) {
    asm volatile("ld.global.nc.v2.u64 {%0, %1}, [%2];"
                 : "=l"(x), "=l"(y) : "l"(p));
}

// 8 windows over a fully in-bounds 72-float segment (16B-aligned).
__device__ __forceinline__ void seg8(const float* __restrict__ p, float a[WPT])
{
    const ulonglong2* p2 = reinterpret_cast<const ulonglong2*>(p);

    ulonglong2 k0 = p2[0], k1 = p2[1];           // pairs 0..3   (elements 0..7)
    ulonglong2 k16 = p2[16], k17 = p2[17];       // pairs 32..35 (elements 64..71)

    // ---- Pass 1: batch-load interior chunks 2..15 (MLP=14), add tree ----
    u64 cc[28];
    #pragma unroll
    for (int c = 0; c < 14; c++)
        ldg2(p2 + 2 + c, cc[2 * c], cc[2 * c + 1]);

    u64 t0 = k0.x, t1 = k0.y, t2 = k1.x, t3 = k1.y;
    #pragma unroll
    for (int j = 0; j < 7; j++) {
        t0 = addx2(t0, cc[4 * j]);
        t1 = addx2(t1, cc[4 * j + 1]);
        t2 = addx2(t2, cc[4 * j + 2]);
        t3 = addx2(t3, cc[4 * j + 3]);
    }
    float lo, hi; upk(addx2(addx2(t0, t1), addx2(t2, t3)), lo, hi);

    float e[8], f[8];
    upk(k0.x,  e[0], e[1]); upk(k0.y,  e[2], e[3]);
    upk(k1.x,  e[4], e[5]); upk(k1.y,  e[6], e[7]);
    upk(k16.x, f[0], f[1]); upk(k16.y, f[2], f[3]);
    upk(k17.x, f[4], f[5]); upk(k17.y, f[6], f[7]);

    const float invk = 1.0f / (float)K_WIN;
    float s = lo + hi;
    float m[WPT]; u64 nm[WPT];
    #pragma unroll
    for (int w = 0; w < WPT; w++) {
        m[w]  = s * invk;
        nm[w] = pk(-m[w], -m[w]);
        s += f[w] - e[w];
    }

    // ---- Pass 2: abs-deviation sums; loads pipelined 2 chunks ahead ----
    u64 A[WPT], B[WPT];
    #pragma unroll
    for (int w = 0; w < WPT; w++) { A[w] = 0ULL; B[w] = 0ULL; }

    u64 cx0, cy0, cx1, cy1;
    ldg2(p2 + 2, cx0, cy0);
    ldg2(p2 + 3, cx1, cy1);
    #pragma unroll
    for (int c = 2; c < 16; c++) {               // pairs 4..31: in all 8 windows
        u64 nx = 0ULL, ny = 0ULL;
        if (c + 2 < 16) ldg2(p2 + c + 2, nx, ny);
        #pragma unroll
        for (int w = 0; w < WPT; w++) {
            A[w] = addx2(A[w], absx2(addx2(cx0, nm[w])));
            B[w] = addx2(B[w], absx2(addx2(cy0, nm[w])));
        }
        cx0 = cx1; cy0 = cy1; cx1 = nx; cy1 = ny;
    }

    const u64 P0 = k0.x,  P1 = k0.y,  P2 = k1.x,  P3 = k1.y;
    const u64 P32 = k16.x, P33 = k16.y, P34 = k17.x;

    // Even windows: extras beyond interior pairs 4..31.
    A[0] = addx2(A[0], absx2(addx2(P0,  nm[0])));
    B[0] = addx2(B[0], absx2(addx2(P1,  nm[0])));
    A[0] = addx2(A[0], absx2(addx2(P2,  nm[0])));
    B[0] = addx2(B[0], absx2(addx2(P3,  nm[0])));

    A[2] = addx2(A[2], absx2(addx2(P1,  nm[2])));
    B[2] = addx2(B[2], absx2(addx2(P2,  nm[2])));
    A[2] = addx2(A[2], absx2(addx2(P3,  nm[2])));
    B[2] = addx2(B[2], absx2(addx2(P32, nm[2])));

    A[4] = addx2(A[4], absx2(addx2(P2,  nm[4])));
    B[4] = addx2(B[4], absx2(addx2(P3,  nm[4])));
    A[4] = addx2(A[4], absx2(addx2(P32, nm[4])));
    B[4] = addx2(B[4], absx2(addx2(P33, nm[4])));

    A[6] = addx2(A[6], absx2(addx2(P3,  nm[6])));
    B[6] = addx2(B[6], absx2(addx2(P32, nm[6])));
    A[6] = addx2(A[6], absx2(addx2(P33, nm[6])));
    B[6] = addx2(B[6], absx2(addx2(P34, nm[6])));

    // Odd windows: full pairs + scalar ends.
    A[1] = addx2(A[1], absx2(addx2(P1,  nm[1])));
    B[1] = addx2(B[1], absx2(addx2(P2,  nm[1])));
    A[1] = addx2(A[1], absx2(addx2(P3,  nm[1])));

    A[3] = addx2(A[3], absx2(addx2(P2,  nm[3])));
    B[3] = addx2(B[3], absx2(addx2(P3,  nm[3])));
    A[3] = addx2(A[3], absx2(addx2(P32, nm[3])));

    A[5] = addx2(A[5], absx2(addx2(P3,  nm[5])));
    B[5] = addx2(B[5], absx2(addx2(P32, nm[5])));
    A[5] = addx2(A[5], absx2(addx2(P33, nm[5])));

    A[7] = addx2(A[7], absx2(addx2(P32, nm[7])));
    B[7] = addx2(B[7], absx2(addx2(P33, nm[7])));
    A[7] = addx2(A[7], absx2(addx2(P34, nm[7])));

    const float ex1 = fabsf(e[1] - m[1]) + fabsf(f[0] - m[1]);
    const float ex3 = fabsf(e[3] - m[3]) + fabsf(f[2] - m[3]);
    const float ex5 = fabsf(e[5] - m[5]) + fabsf(f[4] - m[5]);
    const float ex7 = fabsf(e[7] - m[7]) + fabsf(f[6] - m[7]);

    a[0] = sum2(addx2(A[0], B[0]));
    a[1] = sum2(addx2(A[1], B[1])) + ex1;
    a[2] = sum2(addx2(A[2], B[2]));
    a[3] = sum2(addx2(A[3], B[3])) + ex3;
    a[4] = sum2(addx2(A[4], B[4]));
    a[5] = sum2(addx2(A[5], B[5])) + ex5;
    a[6] = sum2(addx2(A[6], B[6]));
    a[7] = sum2(addx2(A[7], B[7])) + ex7;
}

// Tail fallback (segment not fully in-bounds). Compact loops.
__device__ void seg8_scalar(const float* __restrict__ p, int rem, float a[WPT])
{
    #pragma unroll 1
    for (int w = 0; w < WPT; w++) {
        float s = 0.0f;
        #pragma unroll 1
        for (int j = 0; j < K_WIN; j++) {
            const int idx = w + j;
            s += (idx < rem) ? p[idx] : 0.0f;
        }
        const float m = s * (1.0f / (float)K_WIN);
        float t = 0.0f;
        #pragma unroll 1
        for (int j = 0; j < K_WIN; j++) {
            const int idx = w + j;
            const float x = (idx < rem) ? p[idx] : 0.0f;
            t += fabsf(x - m);
        }
        a[w] = t;
    }
}

__global__ void __launch_bounds__(BLOCK, 2)
smoothness_persist_kernel(const float* __restrict__ yh,
                          const float* __restrict__ yy,
                          int W, int N, int n_sub,
                          float* __restrict__ out, double invW)
{
    __shared__ float  redf[BLOCK / 32];
    __shared__ double redd[BLOCK / 32];
    __shared__ int    s_tile;
    __shared__ int    amLast;

    const int tid  = threadIdx.x;
    const int lane = tid & 31, wid = tid >> 5;

    // Dynamic subtile loop: blocks pull tiles from a global ticket.
    for (;;) {
        if (tid == 0) s_tile = (int)atomicAdd(&g_ticket, 1u);
        __syncthreads();
        const int tile = s_tile;
        __syncthreads();           // s_tile stable before next overwrite
        if (tile >= n_sub) break;

        const int base = tile * SUBTILE;
        const int wend = min(base + SUBTILE, W);
        const int i0   = base + WPT * tid;

        float d2 = 0.0f;
        if (i0 < wend) {
            float a1[WPT], a2[WPT];
            if (N - i0 >= 8 * WPT + 8) {           // 72 elements in-bounds
                seg8(yh + i0, a1);
                seg8(yy + i0, a2);
            } else {
                seg8_scalar(yh + i0, N - i0, a1);
                seg8_scalar(yy + i0, N - i0, a2);
            }
            if (i0 + WPT <= wend) {
                #pragma unroll
                for (int w = 0; w < WPT; w++) {
                    const float d = a1[w] - a2[w];
                    d2 += d * d;
                }
            } else {
                #pragma unroll
                for (int w = 0; w < WPT; w++) {
                    if (i0 + w < wend) {
                        const float d = a1[w] - a2[w];
                        d2 += d * d;
                    }
                }
            }
        }

        // Block reduction -> per-subtile partial (deterministic per tile).
        #pragma unroll
        for (int off = 16; off > 0; off >>= 1)
            d2 += __shfl_down_sync(0xffffffffu, d2, off);
        if (lane == 0) redf[wid] = d2;
        __syncthreads();
        if (wid == 0) {
            float vv = (lane < BLOCK / 32) ? redf[lane] : 0.0f;
            #pragma unroll
            for (int off = 4; off > 0; off >>= 1)
                vv += __shfl_down_sync(0xffffffffu, vv, off);
            if (lane == 0) g_partials[tile] = vv;
        }
        __syncthreads();
    }

    // Arrival + last-block fixed-order reduction.
    if (tid == 0) {
        __threadfence();
        unsigned int c = atomicAdd(&g_count, 1u);
        amLast = (c == (unsigned int)(gridDim.x - 1));
    }
    __syncthreads();

    if (amLast) {
        double s = 0.0;
        #pragma unroll 1
        for (int i = tid; i < n_sub; i += BLOCK)
            s += (double)g_partials[i];
        #pragma unroll
        for (int off = 16; off > 0; off >>= 1)
            s += __shfl_down_sync(0xffffffffu, s, off);
        if (lane == 0) redd[wid] = s;
        __syncthreads();
        if (wid == 0) {
            double vv = (lane < BLOCK / 32) ? redd[lane] : 0.0;
            #pragma unroll
            for (int off = 4; off > 0; off >>= 1)
                vv += __shfl_down_sync(0xffffffffu, vv, off);
            if (lane == 0) {
                out[0] = (float)(vv * invW);
                g_count = 0;                 // reset for next graph replay
                g_ticket = 0;
            }
        }
    }
}

extern "C" void kernel_launch(void* const* d_in, const int* in_sizes, int n_in,
                              void* d_out, int out_size)
{
    const float* yh = (const float*)d_in[0];
    const float* yy = (const float*)d_in[1];
    const int N = in_sizes[0];
    const int W = N - K_WIN - 1;
    const int n_sub = (W + SUBTILE - 1) / SUBTILE;

    smoothness_persist_kernel<<<GRID, BLOCK>>>(yh, yy, W, N, n_sub,
                                               (float*)d_out, 1.0 / (double)W);
}

// round 12
// speedup vs baseline: 1.0910x; 1.0910x over previous
#include <cuda_runtime.h>
#include <cuda_bf16.h>

// SmoothnessLoss: loss = mean_i( (sHat_i - sY_i)^2 ), i in [0, W), W = N-k-1
// s_i = sum_{j<k} | x[i+j] - mean_j |, k = 64.
// Persistent kernel, WPT=4, DUAL-STREAM: yh and yy processed interleaved so
// each warp always has an independent dependency graph + load stream eligible.

#define K_WIN 64
#define BLOCK 256
#define WPT 4
#define STRIDE (BLOCK * WPT)                 // 1024 windows per block-iteration
#define GRID 296                             // 2 blocks/SM x 148 SMs

typedef unsigned long long u64;

__device__ float g_partials[GRID];
__device__ unsigned int g_count = 0;

__device__ __forceinline__ u64 addx2(u64 a, u64 b) {
    u64 r; asm("add.rn.f32x2 %0, %1, %2;" : "=l"(r) : "l"(a), "l"(b)); return r;
}
__device__ __forceinline__ u64 pk(float lo, float hi) {
    u64 r; asm("mov.b64 %0, {%1, %2};" : "=l"(r) : "f"(lo), "f"(hi)); return r;
}
__device__ __forceinline__ void upk(u64 p, float& lo, float& hi) {
    asm("mov.b64 {%0, %1}, %2;" : "=f"(lo), "=f"(hi) : "l"(p));
}
__device__ __forceinline__ u64 absx2(u64 a) { return a & 0x7FFFFFFF7FFFFFFFULL; }
__device__ __forceinline__ float sum2(u64 a) { float l, h; upk(a, l, h); return l + h; }

// Opaque 16B load (prevents cross-pass CSE; placement fixed by program order).
__device__ __forceinline__ void ldg2(const ulonglong2* p, u64& x, u64& y) {
    asm volatile("ld.global.nc.v2.u64 {%0, %1}, [%2];"
                 : "=l"(x), "=l"(y) : "l"(p));
}

#define AACC(acc, v, nmw) acc = addx2(acc, absx2(addx2(v, nmw)))

// 4 windows for BOTH arrays over fully in-bounds 68-float segments.
// Two independent streams (h, y) interleaved throughout.
__device__ __forceinline__ void seg4_dual(const float* __restrict__ ph,
                                          const float* __restrict__ py,
                                          float ah[WPT], float ay[WPT])
{
    const ulonglong2* h2 = reinterpret_cast<const ulonglong2*>(ph);
    const ulonglong2* y2 = reinterpret_cast<const ulonglong2*>(py);

    // Boundary chunks for both arrays.
    ulonglong2 hk0 = h2[0], hk1 = h2[1], hk16 = h2[16];
    ulonglong2 yk0 = y2[0], yk1 = y2[1], yk16 = y2[16];

    // ---- Pass 1: means for both arrays (interleaved 2x4 chains) ----
    u64 ht0 = hk0.x, ht1 = hk0.y, ht2 = hk1.x, ht3 = hk1.y;
    u64 yt0 = yk0.x, yt1 = yk0.y, yt2 = yk1.x, yt3 = yk1.y;
    #pragma unroll
    for (int c = 2; c < 16; c += 2) {
        ulonglong2 hc = h2[c], hd = h2[c + 1];
        ulonglong2 yc = y2[c], yd = y2[c + 1];
        ht0 = addx2(ht0, hc.x);  yt0 = addx2(yt0, yc.x);
        ht1 = addx2(ht1, hc.y);  yt1 = addx2(yt1, yc.y);
        ht2 = addx2(ht2, hd.x);  yt2 = addx2(yt2, yd.x);
        ht3 = addx2(ht3, hd.y);  yt3 = addx2(yt3, yd.y);
    }
    float hlo, hhi, ylo, yhi;
    upk(addx2(addx2(ht0, ht1), addx2(ht2, ht3)), hlo, hhi);
    upk(addx2(addx2(yt0, yt1), addx2(yt2, yt3)), ylo, yhi);

    float he0, he1, he2, he3, hf0, hf1, hf2, hf3;
    float ye0, ye1, ye2, ye3, yf0, yf1, yf2, yf3;
    upk(hk0.x, he0, he1); upk(hk0.y, he2, he3);
    upk(hk16.x, hf0, hf1); upk(hk16.y, hf2, hf3);
    upk(yk0.x, ye0, ye1); upk(yk0.y, ye2, ye3);
    upk(yk16.x, yf0, yf1); upk(yk16.y, yf2, yf3);
    (void)he3; (void)hf3; (void)ye3; (void)yf3;

    const float invk = 1.0f / (float)K_WIN;
    float hm[WPT], ym[WPT];
    u64 hnm[WPT], ynm[WPT];
    {
        const float hd0 = hf0 - he0, hd1 = hf1 - he1, hd2 = hf2 - he2;
        const float yd0 = yf0 - ye0, yd1 = yf1 - ye1, yd2 = yf2 - ye2;
        const float hs0 = hlo + hhi, ys0 = ylo + yhi;
        hm[0] = hs0 * invk;
        hm[1] = (hs0 + hd0) * invk;
        hm[2] = (hs0 + (hd0 + hd1)) * invk;
        hm[3] = (hs0 + ((hd0 + hd1) + hd2)) * invk;
        ym[0] = ys0 * invk;
        ym[1] = (ys0 + yd0) * invk;
        ym[2] = (ys0 + (yd0 + yd1)) * invk;
        ym[3] = (ys0 + ((yd0 + yd1) + yd2)) * invk;
        #pragma unroll
        for (int w = 0; w < WPT; w++) {
            hnm[w] = pk(-hm[w], -hm[w]);
            ynm[w] = pk(-ym[w], -ym[w]);
        }
    }

    // ---- Pass 2: abs-deviation sums, both streams interleaved ----
    u64 HA[WPT], HB[WPT], YA[WPT], YB[WPT];
    #pragma unroll
    for (int w = 0; w < WPT; w++) { HA[w]=0; HB[w]=0; YA[w]=0; YB[w]=0; }

    u64 hx0, hy0, yx0, yy0;            // current chunk (2 pairs) per stream
    ldg2(h2 + 1, hx0, hy0);
    ldg2(y2 + 1, yx0, yy0);
    #pragma unroll
    for (int c = 1; c < 16; c++) {     // pairs 2..31: in all 4 windows
        u64 hx1 = 0, hy1 = 0, yx1 = 0, yy1 = 0;
        if (c + 1 < 16) {              // prefetch next chunk, both streams
            ldg2(h2 + c + 1, hx1, hy1);
            ldg2(y2 + c + 1, yx1, yy1);
        }
        #pragma unroll
        for (int w = 0; w < WPT; w++) {
            AACC(HA[w], hx0, hnm[w]);
            AACC(YA[w], yx0, ynm[w]);
            AACC(HB[w], hy0, hnm[w]);
            AACC(YB[w], yy0, ynm[w]);
        }
        hx0 = hx1; hy0 = hy1; yx0 = yx1; yy0 = yy1;
    }

    // Boundary pairs (window w covers [w, w+64)): same pattern per stream.
    const u64 hP0 = hk0.x, hP1 = hk0.y, hP32 = hk16.x;
    const u64 yP0 = yk0.x, yP1 = yk0.y, yP32 = yk16.x;

    AACC(HA[0], hP0, hnm[0]);  AACC(YA[0], yP0, ynm[0]);
    AACC(HB[0], hP1, hnm[0]);  AACC(YB[0], yP1, ynm[0]);

    AACC(HA[1], hP1, hnm[1]);  AACC(YA[1], yP1, ynm[1]);

    AACC(HA[2], hP1, hnm[2]);  AACC(YA[2], yP1, ynm[2]);
    AACC(HB[2], hP32, hnm[2]); AACC(YB[2], yP32, ynm[2]);

    AACC(HA[3], hP32, hnm[3]); AACC(YA[3], yP32, ynm[3]);

    // Odd-window scalar ends: elements w (odd->hi of pair (w-1)/2... elements 1,64 / 3,66.
    const float hex1 = fabsf(he1 - hm[1]) + fabsf(hf0 - hm[1]);
    const float hex3 = fabsf(he3 - hm[3]) + fabsf(hf2 - hm[3]);
    const float yex1 = fabsf(ye1 - ym[1]) + fabsf(yf0 - ym[1]);
    const float yex3 = fabsf(ye3 - ym[3]) + fabsf(yf2 - ym[3]);

    ah[0] = sum2(addx2(HA[0], HB[0]));
    ah[1] = sum2(addx2(HA[1], HB[1])) + hex1;
    ah[2] = sum2(addx2(HA[2], HB[2]));
    ah[3] = sum2(addx2(HA[3], HB[3])) + hex3;
    ay[0] = sum2(addx2(YA[0], YB[0]));
    ay[1] = sum2(addx2(YA[1], YB[1])) + yex1;
    ay[2] = sum2(addx2(YA[2], YB[2]));
    ay[3] = sum2(addx2(YA[3], YB[3])) + yex3;
}

// Tail fallback (segment not fully in-bounds). Compact loops.
__device__ void seg4_scalar(const float* __restrict__ p, int rem, float a[WPT])
{
    #pragma unroll 1
    for (int w = 0; w < WPT; w++) {
        float s = 0.0f;
        #pragma unroll 1
        for (int j = 0; j < K_WIN; j++) {
            const int idx = w + j;
            s += (idx < rem) ? p[idx] : 0.0f;
        }
        const float m = s * (1.0f / (float)K_WIN);
        float t = 0.0f;
        #pragma unroll 1
        for (int j = 0; j < K_WIN; j++) {
            const int idx = w + j;
            const float x = (idx < rem) ? p[idx] : 0.0f;
            t += fabsf(x - m);
        }
        a[w] = t;
    }
}

__global__ void __launch_bounds__(BLOCK, 2)
smoothness_persist_kernel(const float* __restrict__ yh,
                          const float* __restrict__ yy,
                          int W, int N, int WB,
                          float* __restrict__ out, double invW)
{
    __shared__ float  redf[BLOCK / 32];
    __shared__ double redd[BLOCK / 32];
    __shared__ int    amLast;

    const int tid    = threadIdx.x;
    const int wstart = blockIdx.x * WB;            // multiple of 4
    const int wend   = min(wstart + WB, W);

    float d2 = 0.0f;

    #pragma unroll 1
    for (int i0 = wstart + WPT * tid; i0 < wend; i0 += STRIDE) {
        float a1[WPT], a2[WPT];
        if (N - i0 >= 4 * WPT + 4 + 48) {          // 68 elements fully in-bounds
            seg4_dual(yh + i0, yy + i0, a1, a2);
        } else {
            seg4_scalar(yh + i0, N - i0, a1);
            seg4_scalar(yy + i0, N - i0, a2);
        }
        if (i0 + WPT <= wend) {
            #pragma unroll
            for (int w = 0; w < WPT; w++) {
                const float d = a1[w] - a2[w];
                d2 += d * d;
            }
        } else {
            #pragma unroll
            for (int w = 0; w < WPT; w++) {
                if (i0 + w < wend) {
                    const float d = a1[w] - a2[w];
                    d2 += d * d;
                }
            }
        }
    }

    // Block reduction of d2.
    #pragma unroll
    for (int off = 16; off > 0; off >>= 1)
        d2 += __shfl_down_sync(0xffffffffu, d2, off);

    const int lane = tid & 31, wid = tid >> 5;
    if (lane == 0) redf[wid] = d2;
    __syncthreads();
    if (wid == 0) {
        float vv = (lane < BLOCK / 32) ? redf[lane] : 0.0f;
        #pragma unroll
        for (int off = 4; off > 0; off >>= 1)
            vv += __shfl_down_sync(0xffffffffu, vv, off);
        if (lane == 0) {
            g_partials[blockIdx.x] = vv;
            __threadfence();
            unsigned int c = atomicAdd(&g_count, 1u);
            amLast = (c == (unsigned int)(gridDim.x - 1));
        }
    }
    __syncthreads();

    if (amLast) {
        double s = 0.0;
        #pragma unroll 1
        for (int i = tid; i < GRID; i += BLOCK)
            s += (double)g_partials[i];
        #pragma unroll
        for (int off = 16; off > 0; off >>= 1)
            s += __shfl_down_sync(0xffffffffu, s, off);
        if (lane == 0) redd[wid] = s;
        __syncthreads();
        if (wid == 0) {
            double vv = (lane < BLOCK / 32) ? redd[lane] : 0.0;
            #pragma unroll
            for (int off = 4; off > 0; off >>= 1)
                vv += __shfl_down_sync(0xffffffffu, vv, off);
            if (lane == 0) {
                out[0] = (float)(vv * invW);
                g_count = 0;                 // reset for next graph replay
            }
        }
    }
}

extern "C" void kernel_launch(void* const* d_in, const int* in_sizes, int n_in,
                              void* d_out, int out_size)
{
    const float* yh = (const float*)d_in[0];
    const float* yy = (const float*)d_in[1];
    const int N = in_sizes[0];
    const int W = N - K_WIN - 1;
    int WB = (W + GRID - 1) / GRID;
    WB = (WB + 3) & ~3;                          // multiple of 4 (alignment + WPT)

    smoothness_persist_kernel<<<GRID, BLOCK>>>(yh, yy, W, N, WB,
                                               (float*)d_out, 1.0 / (double)W);
}

// round 13
// speedup vs baseline: 1.1983x; 1.0983x over previous
#include <cuda_runtime.h>
#include <cuda_bf16.h>

// SmoothnessLoss: loss = mean_i( (sHat_i - sY_i)^2 ), i in [0, W), W = N-k-1
// s_i = sum_{j<k} | x[i+j] - mean_j |, k = 64.
// Pair identity: |a-m|+|b-m| = max(|a-b|, |(a+b)-2m|). Per pair precompute
// s=a+b, d=a-b once (shared by 8 windows); per pair-window only 3 instrs
// (FADD t, FMNMX with |ops|, FADD acc). Each thread: 8 windows spaced 2,
// thread parity picks the element pairing (scalar reads of float4 halves).

#define K_WIN 64
#define BLOCK 256
#define WPT 8
#define SPAN 16                               // window span per thread
#define STRIDE ((BLOCK / 2) * SPAN)           // 2048 windows per block-iter
#define GRID 296                              // 2 blocks/SM x 148 SMs

__device__ float g_partials[GRID];
__device__ unsigned int g_count = 0;

// 8 windows (spacing 2) over elements [eb, eb+80). par in {0,1} selects the
// pairing: pair p = elements (2p+par, 2p+par+1) relative to eb.
// Window j (j=0..7) = pairs [j, j+32).  39 pairs total (p = 0..38).
__device__ __forceinline__ void seg8_pairs(const float4* __restrict__ f4,
                                           int par, float a[WPT])
{
    float4 F[20];
    #pragma unroll
    for (int q = 0; q < 20; q++) F[q] = f4[q];

    float s[39], d[39];
    if (par == 0) {
        #pragma unroll
        for (int q = 0; q < 20; q++) {
            if (2 * q < 39)     { s[2*q]   = F[q].x + F[q].y; d[2*q]   = F[q].x - F[q].y; }
            if (2 * q + 1 < 39) { s[2*q+1] = F[q].z + F[q].w; d[2*q+1] = F[q].z - F[q].w; }
        }
    } else {
        #pragma unroll
        for (int q = 0; q < 20; q++) {
            if (2 * q < 39)     { s[2*q]   = F[q].y + F[q].z;     d[2*q]   = F[q].y - F[q].z; }
            if (2 * q + 1 < 39) { s[2*q+1] = F[q].w + F[q+1].x;   d[2*q+1] = F[q].w - F[q+1].x; }
        }
    }

    // Window sums from pair sums: sw(0) = sum s[0..31], slide by one pair.
    float q0 = s[0], q1 = s[1], q2 = s[2], q3 = s[3];
    #pragma unroll
    for (int p = 1; p < 8; p++) {
        q0 += s[4*p];
        q1 += s[4*p+1];
        q2 += s[4*p+2];
        q3 += s[4*p+3];
    }
    float sw = (q0 + q1) + (q2 + q3);

    float twoM[WPT];
    #pragma unroll
    for (int j = 0; j < WPT; j++) {
        twoM[j] = sw * (1.0f / 32.0f);        // 2 * mean  (mean = sw/64)
        sw += s[j + 32] - s[j];
    }

    // Pass 2: per window, 32 pairs, 3 instrs each (FADD, FMNMX|.|, FADD).
    #pragma unroll
    for (int j = 0; j < WPT; j++) {
        const float tm = twoM[j];
        float acc0 = 0.0f, acc1 = 0.0f;
        #pragma unroll
        for (int p = j; p < j + 32; p += 2) {
            float t0 = s[p]     - tm;
            float t1 = s[p + 1] - tm;
            acc0 += fmaxf(fabsf(d[p]),     fabsf(t0));
            acc1 += fmaxf(fabsf(d[p + 1]), fabsf(t1));
        }
        a[j] = acc0 + acc1;
    }
}

// Tail fallback: one window, elements p[0..63] (always in-bounds for w < W).
__device__ float window_scalar(const float* __restrict__ p)
{
    float s0 = 0.f, s1 = 0.f, s2 = 0.f, s3 = 0.f;
    #pragma unroll 1
    for (int i = 0; i < K_WIN; i += 4) {
        s0 += p[i]; s1 += p[i+1]; s2 += p[i+2]; s3 += p[i+3];
    }
    const float m = ((s0 + s1) + (s2 + s3)) * (1.0f / (float)K_WIN);
    float t0 = 0.f, t1 = 0.f;
    #pragma unroll 1
    for (int i = 0; i < K_WIN; i += 2) {
        t0 += fabsf(p[i]   - m);
        t1 += fabsf(p[i+1] - m);
    }
    return t0 + t1;
}

__global__ void __launch_bounds__(BLOCK, 2)
smoothness_persist_kernel(const float* __restrict__ yh,
                          const float* __restrict__ yy,
                          int W, int N, int WB,
                          float* __restrict__ out, double invW)
{
    __shared__ float  redf[BLOCK / 32];
    __shared__ double redd[BLOCK / 32];
    __shared__ int    amLast;

    const int tid    = threadIdx.x;
    const int u      = tid >> 1;
    const int par    = tid & 1;
    const int wstart = blockIdx.x * WB;            // multiple of 16
    const int wend   = min(wstart + WB, W);

    float d2 = 0.0f;

    #pragma unroll 1
    for (int g0 = wstart; g0 < wend; g0 += STRIDE) {
        const int eb = g0 + SPAN * u;              // aligned element base (mult of 16)
        const int w0 = eb + par;                   // first window of this thread
        if (w0 >= wend) continue;

        float a1[WPT], a2[WPT];
        if (eb + 80 <= N) {
            seg8_pairs(reinterpret_cast<const float4*>(yh + eb), par, a1);
            seg8_pairs(reinterpret_cast<const float4*>(yy + eb), par, a2);
        } else {
            #pragma unroll 1
            for (int j = 0; j < WPT; j++) {
                const int w = w0 + 2 * j;
                if (w < wend) {
                    a1[j] = window_scalar(yh + w);
                    a2[j] = window_scalar(yy + w);
                } else { a1[j] = 0.0f; a2[j] = 0.0f; }
            }
        }

        #pragma unroll
        for (int j = 0; j < WPT; j++) {
            if (w0 + 2 * j < wend) {
                const float dd = a1[j] - a2[j];
                d2 += dd * dd;
            }
        }
    }

    // Block reduction of d2.
    #pragma unroll
    for (int off = 16; off > 0; off >>= 1)
        d2 += __shfl_down_sync(0xffffffffu, d2, off);

    const int lane = tid & 31, wid = tid >> 5;
    if (lane == 0) redf[wid] = d2;
    __syncthreads();
    if (wid == 0) {
        float vv = (lane < BLOCK / 32) ? redf[lane] : 0.0f;
        #pragma unroll
        for (int off = 4; off > 0; off >>= 1)
            vv += __shfl_down_sync(0xffffffffu, vv, off);
        if (lane == 0) {
            g_partials[blockIdx.x] = vv;
            __threadfence();
            unsigned int c = atomicAdd(&g_count, 1u);
            amLast = (c == (unsigned int)(gridDim.x - 1));
        }
    }
    __syncthreads();

    if (amLast) {
        // Deterministic final reduction (fixed order/topology).
        double sd = 0.0;
        #pragma unroll 1
        for (int i = tid; i < GRID; i += BLOCK)
            sd += (double)g_partials[i];
        #pragma unroll
        for (int off = 16; off > 0; off >>= 1)
            sd += __shfl_down_sync(0xffffffffu, sd, off);
        if (lane == 0) redd[wid] = sd;
        __syncthreads();
        if (wid == 0) {
            double vv = (lane < BLOCK / 32) ? redd[lane] : 0.0;
            #pragma unroll
            for (int off = 4; off > 0; off >>= 1)
                vv += __shfl_down_sync(0xffffffffu, vv, off);
            if (lane == 0) {
                out[0] = (float)(vv * invW);
                g_count = 0;                 // reset for next graph replay
            }
        }
    }
}

extern "C" void kernel_launch(void* const* d_in, const int* in_sizes, int n_in,
                              void* d_out, int out_size)
{
    const float* yh = (const float*)d_in[0];
    const float* yy = (const float*)d_in[1];
    const int N = in_sizes[0];
    const int W = N - K_WIN - 1;
    int WB = (W + GRID - 1) / GRID;
    WB = (WB + 15) & ~15;                        // multiple of 16 (SPAN/alignment)

    smoothness_persist_kernel<<<GRID, BLOCK>>>(yh, yy, W, N, WB,
                                               (float*)d_out, 1.0 / (double)W);
}